// round 5
// baseline (speedup 1.0000x reference)
#include <cuda_runtime.h>
#include <cstdint>

// Problem constants
#define BATCH   1024
#define IN_H    128
#define IN_W    128
#define WPAD    132
#define NKW     25
#define NK      625
#define KHW     100

// Tiling
#define IGROUPS 5           // blockIdx.y: groups of 5 output rows
#define KL      125         // outputs per block (5 rows * 25 cols)
#define XROWS   30          // padded input rows per 5 output rows
#define XS      152         // x smem row stride (words)
#define IMGW    (XROWS*XS)  // 4560 words per image tile
#define HB      2           // images per buffer
#define BUFW    (HB*IMGW)   // 9120 words
#define DEPTH   3           // pipeline stages
#define BSPLIT  29          // batch stripes: 29*5 = 145 blocks
#define NT      512
#define SMEM_BYTES (DEPTH*BUFW*4)   // 109,440 B

// Extracted weights: g_w[k*100 + dy*10 + dx]
__device__ float g_w[NK * KHW];

__global__ void extract_kernel(const float* __restrict__ W)
{
    int idx = blockIdx.x * blockDim.x + threadIdx.x;
    if (idx >= NK * KHW) return;
    int k  = idx / KHW;
    int d  = idx - k * KHW;
    int dy = d / 10;
    int dx = d - dy * 10;
    int ki = k / NKW;
    int kj = k - ki * NKW;
    int r  = (ki * 5 + dy) * WPAD + (kj * 5 + dx);
    g_w[idx] = W[(size_t)r * NK + k];
}

__device__ __forceinline__ void cp16(unsigned int dst_smem, const float* src, int src_sz)
{
    asm volatile("cp.async.cg.shared.global [%0], [%1], 16, %2;\n"
                 :: "r"(dst_smem), "l"(src), "r"(src_sz));
}

// ---------------------------------------------------------------------------
// 512 threads. Work item p = warp*16 + (lane&15) in [0,250): kl = p%125,
// img = p/125. Lane bit 4 = half: half 0 does kernel rows 0-4, half 1 rows
// 5-9; partners combine via shfl_xor(16). 50 weights live in registers.
// x is triple-buffered via cp.async, 2 images per buffer.
// ---------------------------------------------------------------------------
__global__ __launch_bounds__(NT, 1)
void lc2d_kernel(const float* __restrict__ x,
                 const float* __restrict__ bias,
                 float* __restrict__ out)
{
    extern __shared__ float xs[];
    const unsigned int xs_base = (unsigned int)__cvta_generic_to_shared(xs);

    const int bx  = blockIdx.x;   // 0..28
    const int ig  = blockIdx.y;   // 0..4
    const int tid = threadIdx.x;

    // zero halo columns once (padded cols -2,-1,130,131 of every staged row)
    for (int idx = tid; idx < DEPTH * HB * XROWS; idx += NT) {
        float* p = &xs[idx * XS];
        p[2] = 0.f; p[3] = 0.f; p[132] = 0.f; p[133] = 0.f;
    }

    const int lane = tid & 31;
    const int half = lane >> 4;                     // 0 or 1
    const int p    = (tid >> 5) * 16 + (lane & 15); // 0..255
    const bool pv  = p < 250;
    const int pc   = pv ? p : 249;
    const int kl   = pc % 125;
    const int img  = pc / 125;                      // 0 or 1
    const int il   = kl / 25;
    const int jj   = kl - il * 25;

    // 50 weights into registers (rows half*5 .. half*5+4)
    float wreg[50];
    {
        const float2* wg = reinterpret_cast<const float2*>(
            g_w + (size_t)(ig * KL + kl) * KHW + half * 50);
        #pragma unroll
        for (int j = 0; j < 25; ++j) {
            float2 v = __ldg(&wg[j]);
            wreg[2 * j] = v.x; wreg[2 * j + 1] = v.y;
        }
    }
    const float bv = __ldg(&bias[ig * KL + kl]);

    const int r0       = ig * 25 - 2;
    const int nb_total = (BATCH - 1 - bx) / BSPLIT + 1;   // 35 or 36
    const int NG       = (nb_total + HB - 1) / HB;        // 18

    const int xoff = (il * 5 + half * 5) * XS + jj * 5 + 2;

    // fill one buffer (2 images) for group hg
    auto fill = [&](int buf, int hg) {
        for (int idx = tid; idx < HB * XROWS * 32; idx += NT) {
            int bl  = idx / (XROWS * 32);
            int rem = idx - bl * (XROWS * 32);
            int rr  = rem >> 5;
            int c4  = rem & 31;
            int t   = hg * HB + bl;
            int r   = r0 + rr;
            bool v  = (t < nb_total) & (r >= 0) & (r < IN_H);
            const float* src = v
                ? x + (size_t)(bx + t * BSPLIT) * (IN_H * IN_W) + r * IN_W + c4 * 4
                : x;
            unsigned int dst = xs_base +
                (unsigned int)(buf * BUFW + bl * IMGW + rr * XS + 4 + c4 * 4) * 4u;
            cp16(dst, src, v ? 16 : 0);
        }
        asm volatile("cp.async.commit_group;\n");
    };

    // prologue: fill all DEPTH buffers
    fill(0, 0);
    fill(1, 1);
    fill(2, 2);

    int buf = 0;
    for (int g = 0; g < NG; ++g) {
        // wait until buffer g is complete: allowed pending = min(2, NG-1-g)
        int pend = NG - 1 - g;
        if (pend >= 2)      asm volatile("cp.async.wait_group 2;\n");
        else if (pend == 1) asm volatile("cp.async.wait_group 1;\n");
        else                asm volatile("cp.async.wait_group 0;\n");
        __syncthreads();

        {
            const float* xp = xs + buf * BUFW + img * IMGW + xoff;
            float a0 = 0.f, a1 = 0.f;
            #pragma unroll
            for (int d5 = 0; d5 < 5; ++d5) {
                const float* row = xp + d5 * XS;
                const float* wr  = wreg + d5 * 10;
                #pragma unroll
                for (int dx = 0; dx < 10; dx += 2) {
                    a0 = fmaf(row[dx    ], wr[dx    ], a0);
                    a1 = fmaf(row[dx + 1], wr[dx + 1], a1);
                }
            }
            float a = a0 + a1;
            a += __shfl_xor_sync(0xffffffffu, a, 16);
            int t = g * HB + img;
            if (pv && half == 0 && t < nb_total)
                out[(size_t)(bx + t * BSPLIT) * NK + ig * KL + kl] = a + bv;
        }
        __syncthreads();

        if (g + DEPTH < NG) fill(buf, g + DEPTH);
        buf = (buf == DEPTH - 1) ? 0 : buf + 1;
    }
}

// ---------------------------------------------------------------------------
extern "C" void kernel_launch(void* const* d_in, const int* in_sizes, int n_in,
                              void* d_out, int out_size)
{
    const float* x    = (const float*)d_in[0];   // [1024,128,128]
    const float* W    = (const float*)d_in[1];   // [17424,625]
    const float* bias = (const float*)d_in[2];   // [25,25]
    float* out = (float*)d_out;                  // [1024,25,25]

    cudaFuncSetAttribute(lc2d_kernel,
                         cudaFuncAttributeMaxDynamicSharedMemorySize, SMEM_BYTES);

    extract_kernel<<<(NK * KHW + 255) / 256, 256>>>(W);

    dim3 grid(BSPLIT, IGROUPS);
    lc2d_kernel<<<grid, 512, SMEM_BYTES>>>(x, bias, out);
}

// round 6
// speedup vs baseline: 1.2039x; 1.2039x over previous
#include <cuda_runtime.h>
#include <cstdint>

// Problem constants
#define BATCH   1024
#define IN_H    128
#define IN_W    128
#define WPAD    132
#define NKW     25
#define NK      625
#define KHW     100

// Tiling
#define IGROUPS 5           // blockIdx.y: groups of 5 output rows
#define KL      125         // outputs per block (5 rows * 25 cols)
#define XROWS   30          // padded input rows per 5 output rows
#define XS      152         // x smem row stride (words), mult of 4
#define IMGW    (XROWS*XS)  // 4560 words per image tile
#define HB      2           // images per buffer
#define BUFW    (HB*IMGW)   // 9120 words
#define DEPTH   2           // pipeline stages
#define BSPLIT  58          // batch stripes: 58*5 = 290 blocks = 2 per SM
#define NT      128
#define SMEM_BYTES (DEPTH*BUFW*4)   // 72,960 B per block (x2 blocks = 146KB/SM)

// Extracted weights: g_w[k*100 + dy*10 + dx]
__device__ float g_w[NK * KHW];

__global__ void extract_kernel(const float* __restrict__ W)
{
    int idx = blockIdx.x * blockDim.x + threadIdx.x;
    if (idx >= NK * KHW) return;
    int k  = idx / KHW;
    int d  = idx - k * KHW;
    int dy = d / 10;
    int dx = d - dy * 10;
    int ki = k / NKW;
    int kj = k - ki * NKW;
    int r  = (ki * 5 + dy) * WPAD + (kj * 5 + dx);
    g_w[idx] = W[(size_t)r * NK + k];
}

__device__ __forceinline__ void cp16(unsigned int dst_smem, const float* src, int src_sz)
{
    asm volatile("cp.async.cg.shared.global [%0], [%1], 16, %2;\n"
                 :: "r"(dst_smem), "l"(src), "r"(src_sz));
}

// ---------------------------------------------------------------------------
// 128 threads; thread kl (<125) owns one output position's 100 weights in
// registers and computes 2 images per buffer. Double-buffered cp.async.
// Two blocks co-resident per SM overlap each other's barrier/memory stalls.
// ---------------------------------------------------------------------------
__global__ __launch_bounds__(NT, 2)
void lc2d_kernel(const float* __restrict__ x,
                 const float* __restrict__ bias,
                 float* __restrict__ out)
{
    extern __shared__ float xs[];
    const unsigned int xs_base = (unsigned int)__cvta_generic_to_shared(xs);

    const int bx  = blockIdx.x;   // 0..57
    const int ig  = blockIdx.y;   // 0..4
    const int tid = threadIdx.x;  // 0..127

    // zero halo columns once (padded cols -2,-1,130,131 of every staged row)
    for (int idx = tid; idx < DEPTH * HB * XROWS; idx += NT) {
        float* p = &xs[idx * XS];
        p[2] = 0.f; p[3] = 0.f; p[132] = 0.f; p[133] = 0.f;
    }

    const int kl  = tid < KL ? tid : KL - 1;
    const bool tv = tid < KL;
    const int il  = kl / 25;
    const int jj  = kl - il * 25;

    // ---- 100 weights into registers ----
    float4 w4[25];
    {
        const float4* wg = reinterpret_cast<const float4*>(g_w) + (ig * KL + kl) * 25;
        #pragma unroll
        for (int j = 0; j < 25; ++j) w4[j] = __ldg(&wg[j]);
    }
    const float bv = __ldg(&bias[ig * KL + kl]);

    const int r0       = ig * 25 - 2;
    const int nb_total = (BATCH - 1 - bx) / BSPLIT + 1;   // 17 or 18
    const int NG       = (nb_total + HB - 1) / HB;        // 9

    const int xoff = (il * 5) * XS + jj * 5 + 2;

    // fill one buffer (2 images) for group hg: 1920 float4 = 15/thread
    auto fill = [&](int buf, int hg) {
        #pragma unroll
        for (int i = 0; i < 15; ++i) {
            int idx = tid + i * NT;               // < 1920
            int bl  = idx / (XROWS * 32);
            int rem = idx - bl * (XROWS * 32);
            int rr  = rem >> 5;
            int c4  = rem & 31;
            int t   = hg * HB + bl;
            int r   = r0 + rr;
            bool v  = (t < nb_total) & (r >= 0) & (r < IN_H);
            const float* src = v
                ? x + (size_t)(bx + t * BSPLIT) * (IN_H * IN_W) + r * IN_W + c4 * 4
                : x;
            unsigned int dst = xs_base +
                (unsigned int)(buf * BUFW + bl * IMGW + rr * XS + 4 + c4 * 4) * 4u;
            cp16(dst, src, v ? 16 : 0);
        }
        asm volatile("cp.async.commit_group;\n");
    };

    fill(0, 0);
    fill(1, 1);

    for (int g = 0; g < NG; ++g) {
        if (g == NG - 1) asm volatile("cp.async.wait_group 0;\n");
        else             asm volatile("cp.async.wait_group 1;\n");
        __syncthreads();

        const int buf = g & 1;
        {
            const float* xpA = xs + buf * BUFW + xoff;
            const float* xpB = xpA + IMGW;
            float a0 = 0.f, a1 = 0.f;
            const float* wf = reinterpret_cast<const float*>(w4);
            #pragma unroll
            for (int dy = 0; dy < 10; ++dy) {
                #pragma unroll
                for (int dx = 0; dx < 10; ++dx) {
                    float w = wf[dy * 10 + dx];
                    int   o = dy * XS + dx;
                    a0 = fmaf(xpA[o], w, a0);
                    a1 = fmaf(xpB[o], w, a1);
                }
            }
            int tA = g * HB;
            int ob = ig * KL + kl;
            if (tv && tA < nb_total)
                out[(size_t)(bx + tA * BSPLIT) * NK + ob] = a0 + bv;
            if (tv && tA + 1 < nb_total)
                out[(size_t)(bx + (tA + 1) * BSPLIT) * NK + ob] = a1 + bv;
        }
        __syncthreads();

        if (g + DEPTH < NG) fill(buf, g + DEPTH);
    }
}

// ---------------------------------------------------------------------------
extern "C" void kernel_launch(void* const* d_in, const int* in_sizes, int n_in,
                              void* d_out, int out_size)
{
    const float* x    = (const float*)d_in[0];   // [1024,128,128]
    const float* W    = (const float*)d_in[1];   // [17424,625]
    const float* bias = (const float*)d_in[2];   // [25,25]
    float* out = (float*)d_out;                  // [1024,25,25]

    cudaFuncSetAttribute(lc2d_kernel,
                         cudaFuncAttributeMaxDynamicSharedMemorySize, SMEM_BYTES);

    extract_kernel<<<(NK * KHW + 255) / 256, 256>>>(W);

    dim3 grid(BSPLIT, IGROUPS);
    lc2d_kernel<<<grid, NT, SMEM_BYTES>>>(x, bias, out);
}